// round 4
// baseline (speedup 1.0000x reference)
#include <cuda_runtime.h>

#define N_VOX        1024
#define NUM_RAYS     2048
#define N_SH         9
#define NS           8
#define THREADS      128           // 4 warps cooperating on ONE ray
#define WARPS        4
#define VOX_PER_WARP (N_VOX / WARPS)   // 256 -> 8 tests per lane
#define CAP          128
#define CHUNKS       (CAP / 32)
#define EARLY_STOP_T 0.01f
#define FAR_PLANE    100.0f
#define FULL         0xffffffffu

// Packed per-voxel data, filled by pack_kernel each launch.
__device__ float4 g_box[N_VOX];     // cx, cy, cz, half
__device__ float  g_sigma[N_VOX];   // exp(density)

__global__ void pack_kernel(const float* __restrict__ positions,
                            const float* __restrict__ sizes,
                            const float* __restrict__ densities) {
    const int v = blockIdx.x * 256 + threadIdx.x;
    if (v < N_VOX) {
        g_box[v] = make_float4(positions[v * 3 + 0],
                               positions[v * 3 + 1],
                               positions[v * 3 + 2],
                               0.5f * sizes[v]);
        g_sigma[v] = expf(densities[v]);
    }
}

// float -> order-preserving uint32 (ascending float == ascending uint)
__device__ __forceinline__ unsigned f2u(float f) {
    unsigned u = __float_as_uint(f);
    return (u & 0x80000000u) ? ~u : (u | 0x80000000u);
}

__global__ void __launch_bounds__(THREADS)
voxel_raster_kernel(const float* __restrict__ colors,      // [N, 27]
                    const float* __restrict__ ray_o,       // [B,3]
                    const float* __restrict__ ray_d,       // [B,3]
                    float* __restrict__ out)               // rgb[3B] | depth[B] | weight[B]
{
    __shared__ unsigned long long s_keys[CAP];
    __shared__ float s_tf_src[CAP];
    __shared__ float s_tf_dst[CAP];
    __shared__ int   s_cnt;

    const int b    = blockIdx.x;
    const int warp = threadIdx.x >> 5;
    const int lane = threadIdx.x & 31;

    if (threadIdx.x == 0) s_cnt = 0;
    __syncthreads();

    const float ox = ray_o[b * 3 + 0];
    const float oy = ray_o[b * 3 + 1];
    const float oz = ray_o[b * 3 + 2];
    const float dx = ray_d[b * 3 + 0];
    const float dy = ray_d[b * 3 + 1];
    const float dz = ray_d[b * 3 + 2];
    const float ix = 1.0f / dx, iy = 1.0f / dy, iz = 1.0f / dz;
    const float nx = -ox * ix, ny = -oy * iy, nz = -oz * iz;
    const float ax = fabsf(ix), ay = fabsf(iy), az = fabsf(iz);

    // ---------------- Phase 1: slab tests, 1 LDG.128 per voxel ----------------
    #pragma unroll
    for (int i = 0; i < VOX_PER_WARP / 32; i++) {
        const int v = warp * VOX_PER_WARP + i * 32 + lane;
        const float4 bv = g_box[v];

        const float tcx = fmaf(bv.x, ix, nx);
        const float tcy = fmaf(bv.y, iy, ny);
        const float tcz = fmaf(bv.z, iz, nz);
        const float hx = bv.w * ax, hy = bv.w * ay, hz = bv.w * az;

        const float tn = fmaxf(fmaxf(tcx - hx, tcy - hy), tcz - hz);
        const float tf = fminf(fminf(tcx + hx, tcy + hy), tcz + hz);

        if (tf > tn && tf > 0.0f) {
            const int slot = atomicAdd(&s_cnt, 1);
            if (slot < CAP) {
                s_keys[slot]   = ((unsigned long long)f2u(tn) << 32) | (unsigned)v;
                s_tf_src[slot] = tf;
            }
        }
    }
    __syncthreads();

    // ---------------- Phases 2+3: warp 0 only ----------------
    if (warp != 0) return;

    const int n = min(s_cnt, CAP);

    // ---- rank sort by (tn, voxel idx); keys are unique 64-bit ----
    {
        unsigned long long myk[CHUNKS];
        float mytf[CHUNKS];
        int   myr[CHUNKS];
        #pragma unroll
        for (int c = 0; c < CHUNKS; c++) {
            const int e = c * 32 + lane;
            myr[c] = -1;
            if (e < n) {
                const unsigned long long k = s_keys[e];
                int r = 0;
                for (int j = 0; j < n; j++) r += (s_keys[j] < k);
                myk[c]  = k;
                mytf[c] = s_tf_src[e];
                myr[c]  = r;
            }
        }
        __syncwarp();
        #pragma unroll
        for (int c = 0; c < CHUNKS; c++)
            if (myr[c] >= 0) { s_keys[myr[c]] = myk[c]; s_tf_dst[myr[c]] = mytf[c]; }
        __syncwarp();
    }

    // SH degree-2 basis, reference order: [1, y, z, x, xy, yz, 3z^2-1, xz, x^2-y^2]
    float sh[N_SH];
    sh[0] = 1.0f;
    sh[1] = dy;  sh[2] = dz;  sh[3] = dx;
    sh[4] = dx * dy;  sh[5] = dy * dz;
    sh[6] = 3.0f * dz * dz - 1.0f;
    sh[7] = dx * dz;  sh[8] = dx * dx - dy * dy;

    // ---- warp-parallel composite: prefix-product scan per 32-chunk ----
    float T_carry = 1.0f;
    float rA = 0.0f, gA = 0.0f, bA = 0.0f, dA = 0.0f, wA = 0.0f;

    for (int base = 0; base < n; base += 32) {
        const int e = base + lane;
        float ws = 0.0f, dp = 0.0f, cr = 0.0f, cg = 0.0f, cb = 0.0f;

        if (e < n) {
            const unsigned long long key = s_keys[e];
            const unsigned v  = (unsigned)(key & 0xFFFFFFFFu);
            unsigned tu = (unsigned)(key >> 32);
            const float tn = __uint_as_float((tu & 0x80000000u) ? (tu & 0x7FFFFFFFu) : ~tu);
            const float tf = s_tf_dst[e];

            const float sigma = g_sigma[v];
            const float span  = tf - tn;
            const float delta = span * (1.0f / (float)NS);
            const float alpha = 1.0f - expf(-sigma * delta);
            const float bse   = 1.0f - alpha + 1e-8f;

            float pw = 1.0f;
            #pragma unroll
            for (int s = 0; s < NS; s++) {
                const float w  = alpha * pw;
                const float ts = tn + span * ((float)s / (float)(NS - 1));
                ws += w;
                dp += w * ts;
                pw *= bse;
            }

            const float* c = colors + v * (3 * N_SH);
            float a0 = 0.0f, a1 = 0.0f, a2 = 0.0f;
            #pragma unroll
            for (int k = 0; k < N_SH; k++) {
                a0 += sh[k] * c[k];
                a1 += sh[k] * c[N_SH + k];
                a2 += sh[k] * c[2 * N_SH + k];
            }
            cr = 1.0f / (1.0f + expf(-a0));
            cg = 1.0f / (1.0f + expf(-a1));
            cb = 1.0f / (1.0f + expf(-a2));
        }

        // inclusive prefix product of one_m (inactive lanes contribute 1.0)
        float pp = 1.0f - ws;
        #pragma unroll
        for (int off = 1; off < 32; off <<= 1) {
            const float vv = __shfl_up_sync(FULL, pp, off);
            if (lane >= off) pp *= vv;
        }
        float ex = __shfl_up_sync(FULL, pp, 1);
        if (lane == 0) ex = 1.0f;
        const float Tb = T_carry * ex;

        const float procf   = (Tb >= EARLY_STOP_T) ? 1.0f : 0.0f;
        const float contrib = Tb * ws * procf;
        rA += contrib * cr;
        gA += contrib * cg;
        bA += contrib * cb;
        dA += Tb * procf * dp;
        wA += contrib;

        T_carry *= __shfl_sync(FULL, pp, 31);
        if (T_carry < EARLY_STOP_T && base + 32 < n) break;  // all later proc = 0
    }

    // warp reductions
    #pragma unroll
    for (int off = 16; off > 0; off >>= 1) {
        rA += __shfl_down_sync(FULL, rA, off);
        gA += __shfl_down_sync(FULL, gA, off);
        bA += __shfl_down_sync(FULL, bA, off);
        dA += __shfl_down_sync(FULL, dA, off);
        wA += __shfl_down_sync(FULL, wA, off);
    }

    if (lane == 0) {
        out[b * 3 + 0] = rA;
        out[b * 3 + 1] = gA;
        out[b * 3 + 2] = bA;
        out[NUM_RAYS * 3 + b] = (n > 0) ? dA : FAR_PLANE;   // has_hit == (n > 0)
        out[NUM_RAYS * 4 + b] = wA;
    }
}

extern "C" void kernel_launch(void* const* d_in, const int* in_sizes, int n_in,
                              void* d_out, int out_size) {
    const float* positions = (const float*)d_in[0];
    const float* sizes     = (const float*)d_in[1];
    const float* densities = (const float*)d_in[2];
    const float* colors    = (const float*)d_in[3];
    const float* ray_o     = (const float*)d_in[4];
    const float* ray_d     = (const float*)d_in[5];
    float* out = (float*)d_out;

    pack_kernel<<<(N_VOX + 255) / 256, 256>>>(positions, sizes, densities);
    voxel_raster_kernel<<<NUM_RAYS, THREADS>>>(colors, ray_o, ray_d, out);
}

// round 5
// speedup vs baseline: 1.1831x; 1.1831x over previous
#include <cuda_runtime.h>

#define N_VOX        1024
#define NUM_RAYS     2048
#define N_SH         9
#define NS           8
#define THREADS      128           // 4 warps cooperating on ONE ray
#define WARPS        4
#define VOX_PER_WARP (N_VOX / WARPS)   // 256 -> 8 tests per lane
#define CAP          128
#define CHUNKS       (CAP / 32)
#define EARLY_STOP_T 0.01f
#define FAR_PLANE    100.0f
#define FULL         0xffffffffu

// float -> order-preserving uint32 (ascending float == ascending uint)
__device__ __forceinline__ unsigned f2u(float f) {
    unsigned u = __float_as_uint(f);
    return (u & 0x80000000u) ? ~u : (u | 0x80000000u);
}

__global__ void __launch_bounds__(THREADS)
voxel_raster_kernel(const float* __restrict__ positions,   // [N,3]
                    const float* __restrict__ sizes,       // [N]
                    const float* __restrict__ densities,   // [N]
                    const float* __restrict__ colors,      // [N, 27]
                    const float* __restrict__ ray_o,       // [B,3]
                    const float* __restrict__ ray_d,       // [B,3]
                    float* __restrict__ out)               // rgb[3B] | depth[B] | weight[B]
{
    __shared__ unsigned long long s_keys[CAP];
    __shared__ float s_tf_src[CAP];
    __shared__ float s_tf_dst[CAP];
    __shared__ int   s_cnt;

    const int b    = blockIdx.x;
    const int warp = threadIdx.x >> 5;
    const int lane = threadIdx.x & 31;

    if (threadIdx.x == 0) s_cnt = 0;
    __syncthreads();

    const float ox = ray_o[b * 3 + 0];
    const float oy = ray_o[b * 3 + 1];
    const float oz = ray_o[b * 3 + 2];
    const float dx = ray_d[b * 3 + 0];
    const float dy = ray_d[b * 3 + 1];
    const float dz = ray_d[b * 3 + 2];
    const float ix = 1.0f / dx, iy = 1.0f / dy, iz = 1.0f / dz;
    const float nx = -ox * ix, ny = -oy * iy, nz = -oz * iz;
    const float axr = fabsf(ix), ayr = fabsf(iy), azr = fabsf(iz);

    // ---------------- Phase 1: slab tests + ballot-aggregated push ----------------
    #pragma unroll
    for (int i = 0; i < VOX_PER_WARP / 32; i++) {
        const int v = warp * VOX_PER_WARP + i * 32 + lane;

        const float px = positions[v * 3 + 0];
        const float py = positions[v * 3 + 1];
        const float pz = positions[v * 3 + 2];
        const float h  = 0.5f * sizes[v];

        // slab via center/extent: tc +- h*|inv|
        const float tcx = fmaf(px, ix, nx);
        const float tcy = fmaf(py, iy, ny);
        const float tcz = fmaf(pz, iz, nz);
        const float hx = h * axr, hy = h * ayr, hz = h * azr;

        const float tn = fmaxf(fmaxf(tcx - hx, tcy - hy), tcz - hz);
        const float tf = fminf(fminf(tcx + hx, tcy + hy), tcz + hz);

        const bool hit = tf > fmaxf(tn, 0.0f);
        const unsigned mask = __ballot_sync(FULL, hit);
        if (mask) {
            const int leader = __ffs(mask) - 1;
            int base = 0;
            if (lane == leader) base = atomicAdd(&s_cnt, __popc(mask));
            base = __shfl_sync(FULL, base, leader);
            if (hit) {
                const int slot = base + __popc(mask & ((1u << lane) - 1u));
                if (slot < CAP) {
                    s_keys[slot]   = ((unsigned long long)f2u(tn) << 32) | (unsigned)v;
                    s_tf_src[slot] = tf;
                }
            }
        }
    }
    __syncthreads();

    // ---------------- Phases 2+3: warp 0 only ----------------
    if (warp != 0) return;

    const int n = min(s_cnt, CAP);

    // ---- rank sort by (tn, voxel idx); keys are unique 64-bit ----
    {
        unsigned long long myk[CHUNKS];
        float mytf[CHUNKS];
        int   myr[CHUNKS];
        #pragma unroll
        for (int c = 0; c < CHUNKS; c++) {
            const int e = c * 32 + lane;
            myr[c] = -1;
            if (e < n) {
                const unsigned long long k = s_keys[e];
                int r = 0;
                for (int j = 0; j < n; j++) r += (s_keys[j] < k);
                myk[c]  = k;
                mytf[c] = s_tf_src[e];
                myr[c]  = r;
            }
        }
        __syncwarp();
        #pragma unroll
        for (int c = 0; c < CHUNKS; c++)
            if (myr[c] >= 0) { s_keys[myr[c]] = myk[c]; s_tf_dst[myr[c]] = mytf[c]; }
        __syncwarp();
    }

    // SH degree-2 basis, reference order: [1, y, z, x, xy, yz, 3z^2-1, xz, x^2-y^2]
    float sh[N_SH];
    sh[0] = 1.0f;
    sh[1] = dy;  sh[2] = dz;  sh[3] = dx;
    sh[4] = dx * dy;  sh[5] = dy * dz;
    sh[6] = 3.0f * dz * dz - 1.0f;
    sh[7] = dx * dz;  sh[8] = dx * dx - dy * dy;

    // ---- warp-parallel composite: prefix-product scan per 32-chunk ----
    float T_carry = 1.0f;
    float rA = 0.0f, gA = 0.0f, bA = 0.0f, dA = 0.0f, wA = 0.0f;

    for (int base = 0; base < n; base += 32) {
        const int e = base + lane;
        float ws = 0.0f, dp = 0.0f, cr = 0.0f, cg = 0.0f, cb = 0.0f;

        if (e < n) {
            const unsigned long long key = s_keys[e];
            const unsigned v  = (unsigned)(key & 0xFFFFFFFFu);
            unsigned tu = (unsigned)(key >> 32);
            const float tn = __uint_as_float((tu & 0x80000000u) ? (tu & 0x7FFFFFFFu) : ~tu);
            const float tf = s_tf_dst[e];

            const float sigma = expf(densities[v]);
            const float span  = tf - tn;
            const float delta = span * (1.0f / (float)NS);
            const float alpha = 1.0f - expf(-sigma * delta);
            const float bse   = 1.0f - alpha + 1e-8f;

            float pw = 1.0f;
            #pragma unroll
            for (int s = 0; s < NS; s++) {
                const float w  = alpha * pw;
                const float ts = tn + span * ((float)s / (float)(NS - 1));
                ws += w;
                dp += w * ts;
                pw *= bse;
            }

            const float* c = colors + v * (3 * N_SH);
            float a0 = 0.0f, a1 = 0.0f, a2 = 0.0f;
            #pragma unroll
            for (int k = 0; k < N_SH; k++) {
                a0 += sh[k] * c[k];
                a1 += sh[k] * c[N_SH + k];
                a2 += sh[k] * c[2 * N_SH + k];
            }
            cr = 1.0f / (1.0f + expf(-a0));
            cg = 1.0f / (1.0f + expf(-a1));
            cb = 1.0f / (1.0f + expf(-a2));
        }

        // inclusive prefix product of one_m (inactive lanes contribute 1.0)
        float pp = 1.0f - ws;
        #pragma unroll
        for (int off = 1; off < 32; off <<= 1) {
            const float vv = __shfl_up_sync(FULL, pp, off);
            if (lane >= off) pp *= vv;
        }
        float ex = __shfl_up_sync(FULL, pp, 1);
        if (lane == 0) ex = 1.0f;
        const float Tb = T_carry * ex;

        const float procf   = (Tb >= EARLY_STOP_T) ? 1.0f : 0.0f;
        const float contrib = Tb * ws * procf;
        rA += contrib * cr;
        gA += contrib * cg;
        bA += contrib * cb;
        dA += Tb * procf * dp;
        wA += contrib;

        T_carry *= __shfl_sync(FULL, pp, 31);
        if (T_carry < EARLY_STOP_T && base + 32 < n) break;  // all later proc = 0
    }

    // warp reductions
    #pragma unroll
    for (int off = 16; off > 0; off >>= 1) {
        rA += __shfl_down_sync(FULL, rA, off);
        gA += __shfl_down_sync(FULL, gA, off);
        bA += __shfl_down_sync(FULL, bA, off);
        dA += __shfl_down_sync(FULL, dA, off);
        wA += __shfl_down_sync(FULL, wA, off);
    }

    if (lane == 0) {
        out[b * 3 + 0] = rA;
        out[b * 3 + 1] = bA * 0.0f + gA;   // keep ordering explicit (g)
        out[b * 3 + 1] = gA;
        out[b * 3 + 2] = bA;
        out[NUM_RAYS * 3 + b] = (n > 0) ? dA : FAR_PLANE;   // has_hit == (n > 0)
        out[NUM_RAYS * 4 + b] = wA;
    }
}

extern "C" void kernel_launch(void* const* d_in, const int* in_sizes, int n_in,
                              void* d_out, int out_size) {
    const float* positions = (const float*)d_in[0];
    const float* sizes     = (const float*)d_in[1];
    const float* densities = (const float*)d_in[2];
    const float* colors    = (const float*)d_in[3];
    const float* ray_o     = (const float*)d_in[4];
    const float* ray_d     = (const float*)d_in[5];
    float* out = (float*)d_out;

    voxel_raster_kernel<<<NUM_RAYS, THREADS>>>(positions, sizes, densities, colors,
                                               ray_o, ray_d, out);
}